// round 11
// baseline (speedup 1.0000x reference)
#include <cuda_runtime.h>

// SORF fused: out[m] = (1/64) * sum_a alpha . cos( (1/16) H (D_s ⊙ (rep[m,a] @ red[s])) + bias_s )
// ATOMS=7 -> ~296 CTAs = 2/SM balanced single wave.
// Phase 1: GEMV f32x2, reductors once/CTA, 4-row-deep prefetch, tree merge (no atomics).
// Phase 2: warp = (atom, j-half); FWHT(256) registers+shfl; x reloaded per-j from summed
//          projS; bias/alpha/sign loads hoisted to iteration top (covered by shfl chain).

#define ATOMS 7
#define NATOMS 2048
#define MAXCHUNK 300

typedef unsigned long long ull;

__device__ int g_count[4];
__device__ int g_list[4 * NATOMS];
__device__ int g_tabS[MAXCHUNK];
__device__ int g_tabStart[MAXCHUNK];
__device__ int g_nchunks;

__device__ __forceinline__ ull pack2(float a, float b) {
    ull r; asm("mov.b64 %0, {%1, %2};" : "=l"(r) : "f"(a), "f"(b)); return r;
}
__device__ __forceinline__ float2 unpack2(ull v) {
    float2 r; asm("mov.b64 {%0, %1}, %2;" : "=f"(r.x), "=f"(r.y) : "l"(v)); return r;
}
__device__ __forceinline__ void ffma2(ull& acc, ull a, ull b) {
    asm("fma.rn.f32x2 %0, %1, %2, %0;" : "+l"(acc) : "l"(a), "l"(b));
}
#define BFLY(a, b) do { float t_ = (a); (a) = t_ + (b); (b) = t_ - (b); } while (0)

// ---- prep: smem-staged charges, ballot compaction, dense chunk table ----
__global__ void prep_kernel(const int* __restrict__ charges, float* __restrict__ out) {
    __shared__ int chS[NATOMS];
    __shared__ int cntS[4];
    const int tid = threadIdx.x;          // 256 threads
    if (tid < 32) out[tid] = 0.0f;
    #pragma unroll
    for (int i = 0; i < NATOMS / 256; ++i) chS[tid + 256 * i] = charges[tid + 256 * i];
    __syncthreads();
    const int lane = tid & 31;
    const int w = tid >> 5;
    if (w < 4) {
        int cnt = 0;
        const unsigned lt = (1u << lane) - 1u;
        #pragma unroll 1
        for (int base = 0; base < NATOMS; base += 32) {
            int c = chS[base + lane];
            unsigned m = __ballot_sync(0xffffffffu, c == w);
            if (c == w) g_list[w * NATOMS + cnt + __popc(m & lt)] = base + lane;
            cnt += __popc(m);
        }
        if (lane == 0) { g_count[w] = cnt; cntS[w] = cnt; }
    }
    __syncthreads();
    int offs[5];
    offs[0] = 0;
    #pragma unroll
    for (int s = 0; s < 4; ++s) offs[s + 1] = offs[s] + ((cntS[s] + ATOMS - 1) / ATOMS);
    for (int c = tid; c < offs[4]; c += 256) {
        int s = (c >= offs[1]) + (c >= offs[2]) + (c >= offs[3]);
        g_tabS[c] = s;
        g_tabStart[c] = (c - offs[s]) * ATOMS;
    }
    if (tid == 0) g_nchunks = offs[4];
}

__global__ void __launch_bounds__(512, 2) sorf_kernel(
    const float* __restrict__ rep,
    const float* __restrict__ reductors,
    const float* __restrict__ Dmat,
    const float* __restrict__ bias,
    const float* __restrict__ alpha,
    float* __restrict__ out)
{
    const int c = blockIdx.x;
    if (c >= g_nchunks) return;
    const int s = g_tabS[c];
    const int start = g_tabStart[c];
    const int n = g_count[s];
    const int cnt = min(ATOMS, n - start);

    // bufS 28KB: phase1 rep {v,v} pairs -> merge scratch [4][7 atoms][64 quads]
    __shared__ ull bufS[ATOMS * 512];
    __shared__ float projS[ATOMS * 256];      // 7 KB summed projections
    __shared__ unsigned dbitsS[256];          // 32 stacks x 8 words of sign bits
    __shared__ int atomsS[8];
    __shared__ float wpartS[16];

    const int tid = threadIdx.x;
    const int lane = tid & 31;
    const int w = tid >> 5;                   // 16 warps

    if (tid < 8) atomsS[tid] = (tid < cnt) ? g_list[s * NATOMS + start + tid] : -1;
    __syncthreads();

    // rep -> duplicated pairs: repdup[atom][r] = {rep_r, rep_r}; 7 atoms x 128 quads
    #pragma unroll
    for (int it = 0; it < 2; ++it) {
        int idx = tid + 512 * it;
        if (idx < ATOMS * 128) {
            int ai = idx >> 7, q = idx & 127;
            int atom = atomsS[ai];
            float4 v = (atom >= 0) ? ((const float4*)rep)[(size_t)atom * 128 + q]
                                   : make_float4(0.f, 0.f, 0.f, 0.f);
            ull* d = bufS + ai * 512 + q * 4;
            d[0] = pack2(v.x, v.x); d[1] = pack2(v.y, v.y);
            d[2] = pack2(v.z, v.z); d[3] = pack2(v.w, v.w);
        }
    }
    __syncthreads();

    // ---------------- Phase 1: thread = (c4: 64 col-quads, rh: 8 row-slices), all 7 atoms
    const int c4 = tid & 63;
    const int rh = tid >> 6;
    ull acc0[ATOMS], acc1[ATOMS];
    {
        const int r0 = rh * 64;
        const ulonglong2* rbase = (const ulonglong2*)(reductors + (size_t)s * 131072)
                                  + (size_t)r0 * 64 + c4;
        #pragma unroll
        for (int a = 0; a < ATOMS; ++a) { acc0[a] = 0ull; acc1[a] = 0ull; }
        // 4-row-deep prefetch: pair0 = rows {rr,rr+1}, pair1 = rows {rr+2,rr+3}
        ulonglong2 A0 = rbase[0],   B0 = rbase[64];
        ulonglong2 A1 = rbase[128], B1 = rbase[192];
        #pragma unroll 1
        for (int rr = 0; rr < 64; rr += 4) {
            ulonglong2 ca = A0, cb = B0;
            if (rr + 4 < 64) { A0 = rbase[(rr + 4) * 64]; B0 = rbase[(rr + 5) * 64]; }
            {
                const ulonglong2* rp = (const ulonglong2*)(bufS + r0 + rr);
                #pragma unroll
                for (int a = 0; a < ATOMS; ++a) {
                    ulonglong2 p = rp[a * 256];    // broadcast LDS.128, rows rr/rr+1 dup
                    ffma2(acc0[a], p.x, ca.x); ffma2(acc1[a], p.x, ca.y);
                    ffma2(acc0[a], p.y, cb.x); ffma2(acc1[a], p.y, cb.y);
                }
            }
            ca = A1; cb = B1;
            if (rr + 6 < 64) { A1 = rbase[(rr + 6) * 64]; B1 = rbase[(rr + 7) * 64]; }
            {
                const ulonglong2* rp = (const ulonglong2*)(bufS + r0 + rr + 2);
                #pragma unroll
                for (int a = 0; a < ATOMS; ++a) {
                    ulonglong2 p = rp[a * 256];
                    ffma2(acc0[a], p.x, ca.x); ffma2(acc1[a], p.x, ca.y);
                    ffma2(acc0[a], p.y, cb.x); ffma2(acc1[a], p.y, cb.y);
                }
            }
        }
    }
    __syncthreads();   // rep reads done; bufS becomes merge scratch [4][7 atoms][64 quads]

    float4* scratch = (float4*)bufS;
    if (rh >= 4) {
        #pragma unroll
        for (int a = 0; a < ATOMS; ++a) {
            float2 v0 = unpack2(acc0[a]), v1 = unpack2(acc1[a]);
            scratch[(rh - 4) * (ATOMS * 64) + a * 64 + c4] = make_float4(v0.x, v0.y, v1.x, v1.y);
        }
    }
    __syncthreads();
    if (rh < 4) {
        #pragma unroll
        for (int a = 0; a < ATOMS; ++a) {
            int idx = rh * (ATOMS * 64) + a * 64 + c4;
            float4 t = scratch[idx];
            float2 v0 = unpack2(acc0[a]), v1 = unpack2(acc1[a]);
            scratch[idx] = make_float4(t.x + v0.x, t.y + v0.y, t.z + v1.x, t.w + v1.y);
        }
    } else {
        // warps 8..15 build the D sign bitmask meanwhile
        const float* dsrc = Dmat + (size_t)s * 8192;
        #pragma unroll 1
        for (int k = 0; k < 32; ++k) {
            int word = (w - 8) * 32 + k;
            float dv = dsrc[word * 32 + lane];
            unsigned b = __ballot_sync(0xffffffffu, dv < 0.0f);
            if (lane == 0) dbitsS[word] = b;
        }
    }
    __syncthreads();

    // sum the 4 slices -> projS (scaled); 448 threads, one quad each
    if (tid < ATOMS * 64) {
        float4 t0 = scratch[tid];
        float4 t1 = scratch[1 * (ATOMS * 64) + tid];
        float4 t2 = scratch[2 * (ATOMS * 64) + tid];
        float4 t3 = scratch[3 * (ATOMS * 64) + tid];
        ((float4*)projS)[tid] = make_float4(
            (t0.x + t1.x + t2.x + t3.x) * 0.0625f,
            (t0.y + t1.y + t2.y + t3.y) * 0.0625f,
            (t0.z + t1.z + t2.z + t3.z) * 0.0625f,
            (t0.w + t1.w + t2.w + t3.w) * 0.0625f);
    }
    __syncthreads();

    // ---------------- Phase 2: warp = (atom ai, j-half jh); 16 stacks each
    // x[c] holds p = 4*lane+c ; x[4+c] holds p = 128+4*lane+c
    const int ai = w >> 1;                    // 0..7 ; ai==7 idle
    const int jh = w & 1;
    const int atom = (ai < ATOMS) ? atomsS[ai] : -1;
    float pA = 0.f, pB = 0.f;

    if (atom >= 0) {
        const float4* pj4 = (const float4*)(projS + ai * 256);
        const float4* bbase = (const float4*)(bias + (size_t)s * 8192) + lane;
        const float4* abase = (const float4*)alpha + lane;
        const int wsh = 4 * (lane & 7);
        const int widx = lane >> 3;
        const float sg0 = (lane & 1) ? -1.f : 1.f;
        const float sg1 = (lane & 2) ? -1.f : 1.f;
        const float sg2 = (lane & 4) ? -1.f : 1.f;
        const float sg3 = (lane & 8) ? -1.f : 1.f;
        const float sg4 = (lane & 16) ? -1.f : 1.f;

        #pragma unroll 1
        for (int j = 16 * jh; j < 16 * jh + 16; ++j) {
            // hoisted loads: all operands issued before the butterfly chain
            float4 b0 = __ldg(bbase + j * 64);
            float4 b1 = __ldg(bbase + j * 64 + 32);
            float4 a0 = __ldg(abase + j * 64);
            float4 a1 = __ldg(abase + j * 64 + 32);
            unsigned n0 = dbitsS[j * 8 + widx] >> wsh;
            unsigned n1 = dbitsS[j * 8 + 4 + widx] >> wsh;
            float4 xa4 = pj4[lane];
            float4 xb4 = pj4[lane + 32];

            float x0 = __uint_as_float(__float_as_uint(xa4.x) ^ ((n0 << 31) & 0x80000000u));
            float x1 = __uint_as_float(__float_as_uint(xa4.y) ^ ((n0 << 30) & 0x80000000u));
            float x2 = __uint_as_float(__float_as_uint(xa4.z) ^ ((n0 << 29) & 0x80000000u));
            float x3 = __uint_as_float(__float_as_uint(xa4.w) ^ ((n0 << 28) & 0x80000000u));
            float x4 = __uint_as_float(__float_as_uint(xb4.x) ^ ((n1 << 31) & 0x80000000u));
            float x5 = __uint_as_float(__float_as_uint(xb4.y) ^ ((n1 << 30) & 0x80000000u));
            float x6 = __uint_as_float(__float_as_uint(xb4.z) ^ ((n1 << 29) & 0x80000000u));
            float x7 = __uint_as_float(__float_as_uint(xb4.w) ^ ((n1 << 28) & 0x80000000u));

            // register butterflies: h=1, h=2, h=128
            BFLY(x0, x1); BFLY(x2, x3); BFLY(x4, x5); BFLY(x6, x7);
            BFLY(x0, x2); BFLY(x1, x3); BFLY(x4, x6); BFLY(x5, x7);
            BFLY(x0, x4); BFLY(x1, x5); BFLY(x2, x6); BFLY(x3, x7);

            // cross-lane butterflies: h = 4,8,16,32,64
            #define SSTAGE(m, sg)                                                  \
                x0 = fmaf(x0, sg, __shfl_xor_sync(0xffffffffu, x0, m));            \
                x1 = fmaf(x1, sg, __shfl_xor_sync(0xffffffffu, x1, m));            \
                x2 = fmaf(x2, sg, __shfl_xor_sync(0xffffffffu, x2, m));            \
                x3 = fmaf(x3, sg, __shfl_xor_sync(0xffffffffu, x3, m));            \
                x4 = fmaf(x4, sg, __shfl_xor_sync(0xffffffffu, x4, m));            \
                x5 = fmaf(x5, sg, __shfl_xor_sync(0xffffffffu, x5, m));            \
                x6 = fmaf(x6, sg, __shfl_xor_sync(0xffffffffu, x6, m));            \
                x7 = fmaf(x7, sg, __shfl_xor_sync(0xffffffffu, x7, m));
            SSTAGE(1, sg0) SSTAGE(2, sg1) SSTAGE(4, sg2) SSTAGE(8, sg3) SSTAGE(16, sg4)
            #undef SSTAGE

            pA = fmaf(__cosf(x0 + b0.x), a0.x, pA);
            pA = fmaf(__cosf(x1 + b0.y), a0.y, pA);
            pA = fmaf(__cosf(x2 + b0.z), a0.z, pA);
            pA = fmaf(__cosf(x3 + b0.w), a0.w, pA);
            pB = fmaf(__cosf(x4 + b1.x), a1.x, pB);
            pB = fmaf(__cosf(x5 + b1.y), a1.y, pB);
            pB = fmaf(__cosf(x6 + b1.z), a1.z, pB);
            pB = fmaf(__cosf(x7 + b1.w), a1.w, pB);
        }
    }

    float partial = pA + pB;
    #pragma unroll
    for (int o = 16; o; o >>= 1) partial += __shfl_xor_sync(0xffffffffu, partial, o);
    if (lane == 0) wpartS[w] = partial;
    __syncthreads();
    if (jh == 0 && lane == 0 && atom >= 0)
        atomicAdd(&out[atom >> 6], (wpartS[w] + wpartS[w + 1]) * 0.015625f);  // FEAT_NORM
}

extern "C" void kernel_launch(void* const* d_in, const int* in_sizes, int n_in,
                              void* d_out, int out_size) {
    (void)in_sizes; (void)n_in; (void)out_size;
    const float* rep       = (const float*)d_in[0];
    const int*   charges   = (const int*)d_in[1];
    const float* reductors = (const float*)d_in[2];
    const float* Dmat      = (const float*)d_in[3];
    const float* bias      = (const float*)d_in[4];
    const float* alpha     = (const float*)d_in[5];
    float* out = (float*)d_out;

    prep_kernel<<<1, 256>>>(charges, out);
    sorf_kernel<<<MAXCHUNK, 512>>>(rep, reductors, Dmat, bias, alpha, out);
}

// round 12
// speedup vs baseline: 1.6643x; 1.6643x over previous
#include <cuda_runtime.h>

// SORF fused: out[m] = (1/64) * sum_a alpha . cos( (1/16) H (D_s ⊙ (rep[m,a] @ red[s])) + bias_s )
// ATOMS=7 -> ~296 CTAs = 2/SM balanced single wave.
// Phase 1: GEMV f32x2, reductors once/CTA, 2-row prefetch (round-10 proven), tree merge.
// Phase 2: warp = (atom, j-half); FWHT(256) registers+shfl; signs = 1 LOP3/element from
//          D floats in smem (overlay); bias+alpha via L1-hot LDG, hoisted to loop top.

#define ATOMS 7
#define NATOMS 2048
#define MAXCHUNK 300

typedef unsigned long long ull;

__device__ int g_count[4];
__device__ int g_list[4 * NATOMS];
__device__ int g_tabS[MAXCHUNK];
__device__ int g_tabStart[MAXCHUNK];
__device__ int g_nchunks;

__device__ __forceinline__ ull pack2(float a, float b) {
    ull r; asm("mov.b64 %0, {%1, %2};" : "=l"(r) : "f"(a), "f"(b)); return r;
}
__device__ __forceinline__ float2 unpack2(ull v) {
    float2 r; asm("mov.b64 {%0, %1}, %2;" : "=f"(r.x), "=f"(r.y) : "l"(v)); return r;
}
__device__ __forceinline__ void ffma2(ull& acc, ull a, ull b) {
    asm("fma.rn.f32x2 %0, %1, %2, %0;" : "+l"(acc) : "l"(a), "l"(b));
}
#define BFLY(a, b) do { float t_ = (a); (a) = t_ + (b); (b) = t_ - (b); } while (0)
__device__ __forceinline__ float sgnx(float x, float d) {   // x * sign(d): 1 LOP3
    return __uint_as_float(__float_as_uint(x) ^ (__float_as_uint(d) & 0x80000000u));
}

// ---- prep: smem-staged charges, ballot compaction, dense chunk table ----
__global__ void prep_kernel(const int* __restrict__ charges, float* __restrict__ out) {
    __shared__ int chS[NATOMS];
    __shared__ int cntS[4];
    const int tid = threadIdx.x;          // 256 threads
    if (tid < 32) out[tid] = 0.0f;
    #pragma unroll
    for (int i = 0; i < NATOMS / 256; ++i) chS[tid + 256 * i] = charges[tid + 256 * i];
    __syncthreads();
    const int lane = tid & 31;
    const int w = tid >> 5;
    if (w < 4) {
        int cnt = 0;
        const unsigned lt = (1u << lane) - 1u;
        #pragma unroll 1
        for (int base = 0; base < NATOMS; base += 32) {
            int c = chS[base + lane];
            unsigned m = __ballot_sync(0xffffffffu, c == w);
            if (c == w) g_list[w * NATOMS + cnt + __popc(m & lt)] = base + lane;
            cnt += __popc(m);
        }
        if (lane == 0) { g_count[w] = cnt; cntS[w] = cnt; }
    }
    __syncthreads();
    int offs[5];
    offs[0] = 0;
    #pragma unroll
    for (int s = 0; s < 4; ++s) offs[s + 1] = offs[s] + ((cntS[s] + ATOMS - 1) / ATOMS);
    for (int c = tid; c < offs[4]; c += 256) {
        int s = (c >= offs[1]) + (c >= offs[2]) + (c >= offs[3]);
        g_tabS[c] = s;
        g_tabStart[c] = (c - offs[s]) * ATOMS;
    }
    if (tid == 0) g_nchunks = offs[4];
}

__global__ void __launch_bounds__(512, 2) sorf_kernel(
    const float* __restrict__ rep,
    const float* __restrict__ reductors,
    const float* __restrict__ Dmat,
    const float* __restrict__ bias,
    const float* __restrict__ alpha,
    float* __restrict__ out)
{
    const int c = blockIdx.x;
    if (c >= g_nchunks) return;
    const int s = g_tabS[c];
    const int start = g_tabStart[c];
    const int n = g_count[s];
    const int cnt = min(ATOMS, n - start);

    // bufS 32KB multi-use: rep {v,v} pairs (28KB) -> merge scratch (4x7KB) -> D floats (32KB)
    __shared__ ull bufS[4096];
    __shared__ int atomsS[8];
    __shared__ float wpartS[16];

    const int tid = threadIdx.x;
    const int lane = tid & 31;
    const int w = tid >> 5;                   // 16 warps

    if (tid < 8) atomsS[tid] = (tid < cnt) ? g_list[s * NATOMS + start + tid] : -1;
    __syncthreads();

    // rep -> duplicated pairs: repdup[atom][r] = {rep_r, rep_r}; 7 atoms x 128 quads
    #pragma unroll
    for (int it = 0; it < 2; ++it) {
        int idx = tid + 512 * it;
        if (idx < ATOMS * 128) {
            int ai = idx >> 7, q = idx & 127;
            int atom = atomsS[ai];
            float4 v = (atom >= 0) ? ((const float4*)rep)[(size_t)atom * 128 + q]
                                   : make_float4(0.f, 0.f, 0.f, 0.f);
            ull* d = bufS + ai * 512 + q * 4;
            d[0] = pack2(v.x, v.x); d[1] = pack2(v.y, v.y);
            d[2] = pack2(v.z, v.z); d[3] = pack2(v.w, v.w);
        }
    }
    __syncthreads();

    // ---------------- Phase 1: thread = (c4: 64 col-quads, rh: 8 row-slices), all 7 atoms
    const int c4 = tid & 63;
    const int rh = tid >> 6;
    ull acc0[ATOMS], acc1[ATOMS];
    {
        const int r0 = rh * 64;
        const ulonglong2* rbase = (const ulonglong2*)(reductors + (size_t)s * 131072)
                                  + (size_t)r0 * 64 + c4;
        #pragma unroll
        for (int a = 0; a < ATOMS; ++a) { acc0[a] = 0ull; acc1[a] = 0ull; }
        ulonglong2 bufA = rbase[0];
        ulonglong2 bufB = rbase[64];
        #pragma unroll 1
        for (int rr = 0; rr < 64; rr += 2) {
            ulonglong2 ca = bufA, cb = bufB;
            if (rr + 2 < 64) { bufA = rbase[(rr + 2) * 64]; bufB = rbase[(rr + 3) * 64]; }
            const ulonglong2* rp = (const ulonglong2*)(bufS + r0 + rr);
            #pragma unroll
            for (int a = 0; a < ATOMS; ++a) {
                ulonglong2 p = rp[a * 256];    // broadcast LDS.128
                ffma2(acc0[a], p.x, ca.x); ffma2(acc1[a], p.x, ca.y);
                ffma2(acc0[a], p.y, cb.x); ffma2(acc1[a], p.y, cb.y);
            }
        }
    }
    __syncthreads();   // rep reads done; bufS becomes merge scratch [4][7 atoms][64 quads]

    float4* scratch = (float4*)bufS;
    if (rh >= 4) {
        #pragma unroll
        for (int a = 0; a < ATOMS; ++a) {
            float2 v0 = unpack2(acc0[a]), v1 = unpack2(acc1[a]);
            scratch[(rh - 4) * (ATOMS * 64) + a * 64 + c4] = make_float4(v0.x, v0.y, v1.x, v1.y);
        }
    }
    __syncthreads();
    if (rh < 4) {
        #pragma unroll
        for (int a = 0; a < ATOMS; ++a) {
            int idx = rh * (ATOMS * 64) + a * 64 + c4;
            float4 t = scratch[idx];
            float2 v0 = unpack2(acc0[a]), v1 = unpack2(acc1[a]);
            scratch[idx] = make_float4(t.x + v0.x, t.y + v0.y, t.z + v1.x, t.w + v1.y);
        }
    }
    __syncthreads();

    // ---------------- Phase 2 entry: warp (ai, jh); sum 4 slices -> registers
    const int ai = w >> 1;                    // 0..7 ; ai==7 idle
    const int jh = w & 1;
    const int atom = (ai < ATOMS) ? atomsS[ai] : -1;
    float4 xa4 = make_float4(0.f, 0.f, 0.f, 0.f), xb4 = xa4;
    if (atom >= 0) {
        #pragma unroll
        for (int k = 0; k < 4; ++k) {
            float4 ta = scratch[k * (ATOMS * 64) + ai * 64 + lane];
            float4 tb = scratch[k * (ATOMS * 64) + ai * 64 + 32 + lane];
            xa4.x += ta.x; xa4.y += ta.y; xa4.z += ta.z; xa4.w += ta.w;
            xb4.x += tb.x; xb4.y += tb.y; xb4.z += tb.z; xb4.w += tb.w;
        }
        xa4.x *= 0.0625f; xa4.y *= 0.0625f; xa4.z *= 0.0625f; xa4.w *= 0.0625f;
        xb4.x *= 0.0625f; xb4.y *= 0.0625f; xb4.z *= 0.0625f; xb4.w *= 0.0625f;
    }
    __syncthreads();   // slice reads done; overlay D floats into bufS

    {
        float4* dst = (float4*)bufS;
        const float4* src = (const float4*)(Dmat + (size_t)s * 8192);
        #pragma unroll
        for (int it = 0; it < 4; ++it) dst[tid + 512 * it] = src[tid + 512 * it];
    }
    __syncthreads();

    // ---------------- Phase 2 loop: 16 stacks per warp (j-half jh)
    // x[c] holds p = 4*lane+c ; x[4+c] holds p = 128+4*lane+c
    float pA = 0.f, pB = 0.f;
    if (atom >= 0) {
        const float4* dd4 = (const float4*)bufS;
        const float4* bbase = (const float4*)(bias + (size_t)s * 8192) + lane;
        const float4* abase = (const float4*)alpha + lane;
        const float sg0 = (lane & 1) ? -1.f : 1.f;
        const float sg1 = (lane & 2) ? -1.f : 1.f;
        const float sg2 = (lane & 4) ? -1.f : 1.f;
        const float sg3 = (lane & 8) ? -1.f : 1.f;
        const float sg4 = (lane & 16) ? -1.f : 1.f;

        #pragma unroll 1
        for (int j = 16 * jh; j < 16 * jh + 16; ++j) {
            // hoisted global loads (L1-hot), consumed ~100 slots later
            float4 b0 = __ldg(bbase + j * 64);
            float4 b1 = __ldg(bbase + j * 64 + 32);
            float4 a0 = __ldg(abase + j * 64);
            float4 a1 = __ldg(abase + j * 64 + 32);
            float4 d0 = dd4[j * 64 + lane];
            float4 d1 = dd4[j * 64 + 32 + lane];

            float x0 = sgnx(xa4.x, d0.x), x1 = sgnx(xa4.y, d0.y);
            float x2 = sgnx(xa4.z, d0.z), x3 = sgnx(xa4.w, d0.w);
            float x4 = sgnx(xb4.x, d1.x), x5 = sgnx(xb4.y, d1.y);
            float x6 = sgnx(xb4.z, d1.z), x7 = sgnx(xb4.w, d1.w);

            // register butterflies: h=1, h=2, h=128
            BFLY(x0, x1); BFLY(x2, x3); BFLY(x4, x5); BFLY(x6, x7);
            BFLY(x0, x2); BFLY(x1, x3); BFLY(x4, x6); BFLY(x5, x7);
            BFLY(x0, x4); BFLY(x1, x5); BFLY(x2, x6); BFLY(x3, x7);

            // cross-lane butterflies: h = 4,8,16,32,64
            #define SSTAGE(m, sg)                                                  \
                x0 = fmaf(x0, sg, __shfl_xor_sync(0xffffffffu, x0, m));            \
                x1 = fmaf(x1, sg, __shfl_xor_sync(0xffffffffu, x1, m));            \
                x2 = fmaf(x2, sg, __shfl_xor_sync(0xffffffffu, x2, m));            \
                x3 = fmaf(x3, sg, __shfl_xor_sync(0xffffffffu, x3, m));            \
                x4 = fmaf(x4, sg, __shfl_xor_sync(0xffffffffu, x4, m));            \
                x5 = fmaf(x5, sg, __shfl_xor_sync(0xffffffffu, x5, m));            \
                x6 = fmaf(x6, sg, __shfl_xor_sync(0xffffffffu, x6, m));            \
                x7 = fmaf(x7, sg, __shfl_xor_sync(0xffffffffu, x7, m));
            SSTAGE(1, sg0) SSTAGE(2, sg1) SSTAGE(4, sg2) SSTAGE(8, sg3) SSTAGE(16, sg4)
            #undef SSTAGE

            pA = fmaf(__cosf(x0 + b0.x), a0.x, pA);
            pA = fmaf(__cosf(x1 + b0.y), a0.y, pA);
            pA = fmaf(__cosf(x2 + b0.z), a0.z, pA);
            pA = fmaf(__cosf(x3 + b0.w), a0.w, pA);
            pB = fmaf(__cosf(x4 + b1.x), a1.x, pB);
            pB = fmaf(__cosf(x5 + b1.y), a1.y, pB);
            pB = fmaf(__cosf(x6 + b1.z), a1.z, pB);
            pB = fmaf(__cosf(x7 + b1.w), a1.w, pB);
        }
    }

    float partial = pA + pB;
    #pragma unroll
    for (int o = 16; o; o >>= 1) partial += __shfl_xor_sync(0xffffffffu, partial, o);
    if (lane == 0) wpartS[w] = partial;
    __syncthreads();
    if (jh == 0 && lane == 0 && atom >= 0)
        atomicAdd(&out[atom >> 6], (wpartS[w] + wpartS[w + 1]) * 0.015625f);  // FEAT_NORM
}

extern "C" void kernel_launch(void* const* d_in, const int* in_sizes, int n_in,
                              void* d_out, int out_size) {
    (void)in_sizes; (void)n_in; (void)out_size;
    const float* rep       = (const float*)d_in[0];
    const int*   charges   = (const int*)d_in[1];
    const float* reductors = (const float*)d_in[2];
    const float* Dmat      = (const float*)d_in[3];
    const float* bias      = (const float*)d_in[4];
    const float* alpha     = (const float*)d_in[5];
    float* out = (float*)d_out;

    prep_kernel<<<1, 256>>>(charges, out);
    sorf_kernel<<<MAXCHUNK, 512>>>(rep, reductors, Dmat, bias, alpha, out);
}